// round 3
// baseline (speedup 1.0000x reference)
#include <cuda_runtime.h>

#define HH 448
#define WW 512
#define CC 128
#define NCLS 128
#define TW 256
#define KC 16
#define HW (HH*WW)      // 229376
#define CHW (CC*WW)     // 65536

typedef unsigned long long ull;

// Scratch (allocation-free rule: __device__ globals)
__device__ float g_t1[HH*CC*WW];
__device__ float g_t2[HH*CC*WW];
__device__ float g_xr[HH*CC*WW];
__device__ int   g_inds[HW];

__device__ __forceinline__ ull pk2(float v){
    ull r; unsigned u = __float_as_uint(v);
    asm("mov.b64 %0, {%1, %1};" : "=l"(r) : "r"(u));
    return r;
}
__device__ __forceinline__ void fma2(ull& d, ull a, ull b){
    asm("fma.rn.f32x2 %0, %1, %2, %0;" : "+l"(d) : "l"(a), "l"(b));
}
__device__ __forceinline__ float2 up2(ull v){
    unsigned lo, hi;
    asm("mov.b64 {%0, %1}, %2;" : "=r"(lo), "=r"(hi) : "l"(v));
    return make_float2(__uint_as_float(lo), __uint_as_float(hi));
}
__device__ __forceinline__ float lrelu(float v){ return v >= 0.f ? v : 0.01f*v; }

// Core: one CTA computes a 128(O) x 256(W) tile for row h, K=128.
// Xh = input base for this (h, wBase); row k at Xh + k*xRS.
// Wh = weight base for this h (o-major rows of 128 k).
// Accumulators: acc[o][p] are f32x2 pairs; thread covers o0..o0+7 and
// 16 w-columns arranged as 4-float chunks at t4 + 64*j (conflict-free LDS).
__device__ __forceinline__ void gemm_core(
    const float* __restrict__ Xh, size_t xRS,
    const float* __restrict__ Wh,
    float (&Ws)[2][KC][128], float (&Xs)[2][KC][TW],
    ull (&acc)[8][8])
{
    const int tid = threadIdx.x;
    const int og = tid >> 4, wg = tid & 15;
    const int o0 = og << 3, t4 = wg << 2;
    const int xk = tid >> 4;            // Xs load: row within chunk
    const int xc = (tid & 15) << 2;     // Xs load: col base
    const int wq = tid & 3;             // Ws load: k-quad
    const int wo = tid >> 2;            // Ws load: o (0..63, +64)

    float4 xst[4];
    float4 wst[2];

    // prologue: chunk 0
    #pragma unroll
    for (int j = 0; j < 4; ++j)
        xst[j] = *reinterpret_cast<const float4*>(Xh + (size_t)xk * xRS + xc + 64*j);
    wst[0] = *reinterpret_cast<const float4*>(Wh + wo*128 + wq*4);
    wst[1] = *reinterpret_cast<const float4*>(Wh + (wo+64)*128 + wq*4);
    #pragma unroll
    for (int j = 0; j < 4; ++j)
        *reinterpret_cast<float4*>(&Xs[0][xk][xc + 64*j]) = xst[j];
    {
        const float* s0 = &wst[0].x;
        const float* s1 = &wst[1].x;
        #pragma unroll
        for (int i = 0; i < 4; ++i){
            int k = wq*4 + i;
            Ws[0][k][wo ^ (wq<<3)] = s0[i];          // XOR swizzle: conflict-free STS
            Ws[0][k][(wo+64) ^ (wq<<3)] = s1[i];
        }
    }
    __syncthreads();

    int buf = 0;
    #pragma unroll 1
    for (int ch = 0; ch < 8; ++ch){
        if (ch < 7){
            int k0 = (ch+1)*KC;
            #pragma unroll
            for (int j = 0; j < 4; ++j)
                xst[j] = *reinterpret_cast<const float4*>(Xh + (size_t)(k0 + xk) * xRS + xc + 64*j);
            wst[0] = *reinterpret_cast<const float4*>(Wh + wo*128 + k0 + wq*4);
            wst[1] = *reinterpret_cast<const float4*>(Wh + (wo+64)*128 + k0 + wq*4);
        }
        #pragma unroll
        for (int k = 0; k < KC; ++k){
            int wOff = ((k >> 2) & 3) << 3;
            const float4* wr = reinterpret_cast<const float4*>(&Ws[buf][k][o0 ^ wOff]);
            float4 wa = wr[0], wb = wr[1];
            float wv[8] = {wa.x,wa.y,wa.z,wa.w,wb.x,wb.y,wb.z,wb.w};
            ull xp[8];
            #pragma unroll
            for (int j = 0; j < 4; ++j){
                ulonglong2 v = *reinterpret_cast<const ulonglong2*>(&Xs[buf][k][t4 + 64*j]);
                xp[2*j] = v.x; xp[2*j+1] = v.y;
            }
            #pragma unroll
            for (int o = 0; o < 8; ++o){
                ull wp = pk2(wv[o]);
                #pragma unroll
                for (int p = 0; p < 8; ++p) fma2(acc[o][p], xp[p], wp);
            }
        }
        if (ch < 7){
            int nb = buf ^ 1;
            #pragma unroll
            for (int j = 0; j < 4; ++j)
                *reinterpret_cast<float4*>(&Xs[nb][xk][xc + 64*j]) = xst[j];
            const float* s0 = &wst[0].x;
            const float* s1 = &wst[1].x;
            #pragma unroll
            for (int i = 0; i < 4; ++i){
                int k = wq*4 + i;
                Ws[nb][k][wo ^ (wq<<3)] = s0[i];
                Ws[nb][k][(wo+64) ^ (wq<<3)] = s1[i];
            }
            __syncthreads();
            buf = nb;
        }
    }
}

// GEMM + bias + leaky-relu. If dual!=0, blockIdx.x selects (A/B) weight set
// interleaved so both read the same X tile back-to-back (L2 reuse).
__global__ void __launch_bounds__(256,1)
k_gemm_lrelu(const float* __restrict__ X, size_t xHS, size_t xRS,
             const float* __restrict__ WtA, const float* __restrict__ BtA, float* __restrict__ YA,
             const float* __restrict__ WtB, const float* __restrict__ BtB, float* __restrict__ YB,
             int dual)
{
    __shared__ __align__(16) float Ws[2][KC][128];
    __shared__ __align__(16) float Xs[2][KC][TW];
    int bx = blockIdx.x;
    int sel = 0, wTile;
    if (dual){ sel = bx & 1; wTile = bx >> 1; } else wTile = bx;
    const int h = blockIdx.y;
    const int wBase = wTile * TW;
    const float* Wt = sel ? WtB : WtA;
    const float* Bt = sel ? BtB : BtA;
    float* Y = sel ? YB : YA;

    ull acc[8][8];
    #pragma unroll
    for (int o=0;o<8;o++)
        #pragma unroll
        for (int p=0;p<8;p++) acc[o][p] = 0ull;

    const float* Xh = X + (size_t)h*xHS + wBase;
    const float* Wh = Wt + (size_t)h*(128*128);
    gemm_core(Xh, xRS, Wh, Ws, Xs, acc);

    const int tid = threadIdx.x;
    const int og = tid>>4, wg = tid&15;
    const int o0 = og<<3, t4 = wg<<2;
    #pragma unroll
    for (int o=0;o<8;o++){
        float bo = Bt[h*128 + o0 + o];
        float* yo = Y + (size_t)h*CHW + (size_t)(o0+o)*WW + wBase;
        #pragma unroll
        for (int j=0;j<4;j++){
            float2 a = up2(acc[o][2*j]);
            float2 b = up2(acc[o][2*j+1]);
            float4 v;
            v.x = lrelu(a.x + bo); v.y = lrelu(a.y + bo);
            v.z = lrelu(b.x + bo); v.w = lrelu(b.y + bo);
            *reinterpret_cast<float4*>(yo + t4 + 64*j) = v;
        }
    }
}

// Classifier GEMM (129-row weights, rows 0..127 used) + fused in-CTA argmax.
// Tile covers all 128 classes x 256 cols, so argmax never leaves the CTA.
__global__ void __launch_bounds__(256,1)
k_gemm_argmax(const float* __restrict__ X, const float* __restrict__ Wt,
              const float* __restrict__ Bt, int* __restrict__ inds)
{
    __shared__ __align__(16) float Ws[2][KC][128];
    __shared__ __align__(16) float Xs[2][KC][TW];
    const int wTile = blockIdx.x, h = blockIdx.y;
    const int wBase = wTile * TW;

    ull acc[8][8];
    #pragma unroll
    for (int o=0;o<8;o++)
        #pragma unroll
        for (int p=0;p<8;p++) acc[o][p] = 0ull;

    const float* Xh = X + (size_t)h*CHW + wBase;
    const float* Wh = Wt + (size_t)h*(129*128);
    gemm_core(Xh, (size_t)WW, Wh, Ws, Xs, acc);

    const int tid = threadIdx.x;
    const int og = tid>>4, wg = tid&15;
    const int o0 = og<<3, t4 = wg<<2;

    // per-thread argmax over its 8 classes, per column (ascending class order,
    // strict > keeps the first max like jnp.argmax)
    float best[16]; int bidx[16];
    #pragma unroll
    for (int o=0;o<8;o++){
        float bo = Bt[h*129 + o0 + o];
        #pragma unroll
        for (int p=0;p<8;p++){
            float2 f = up2(acc[o][p]);
            float v0 = f.x + bo, v1 = f.y + bo;
            int c0 = 2*p, c1 = c0+1;
            if (o==0){ best[c0]=v0; bidx[c0]=o0; best[c1]=v1; bidx[c1]=o0; }
            else {
                if (v0 > best[c0]){ best[c0]=v0; bidx[c0]=o0+o; }
                if (v1 > best[c1]){ best[c1]=v1; bidx[c1]=o0+o; }
            }
        }
    }
    __syncthreads();   // done reading tiles; reuse smem for reduction

    float* rv = &Xs[0][0][0];                         // [16][256] values (16KB)
    int*   ri = reinterpret_cast<int*>(&Ws[0][0][0]); // [16][256] indices (16KB)
    #pragma unroll
    for (int lc=0; lc<16; ++lc){
        int w = t4 + 64*(lc>>2) + (lc&3);
        rv[og*TW + w] = best[lc];
        ri[og*TW + w] = bidx[lc];
    }
    __syncthreads();
    {
        int w = tid;                 // 256 threads, 256 columns
        float bv = rv[w]; int bi = ri[w];
        #pragma unroll
        for (int g=1; g<16; ++g){    // ascending class groups: ties keep first
            float v = rv[g*TW + w];
            int i = ri[g*TW + w];
            if (v > bv){ bv = v; bi = i; }
        }
        inds[h*WW + wBase + w] = bi;
    }
}

// Final: mask row (class 128 of cl3) + gathered per-pixel 128->4->1 regressor.
// Reproduces the reference's index scramble: rows use n = w*448 + h, while
// inds_r interprets the same flat n as (h2, w2i) on a (448,512) grid.
__global__ void k_final(const float* __restrict__ xr, const float* __restrict__ t2,
                        const float* __restrict__ w_cl3, const float* __restrict__ b_cl3,
                        const int* __restrict__ inds,
                        const float* __restrict__ w2, const float* __restrict__ b2,
                        const float* __restrict__ w3, const float* __restrict__ b3,
                        float* __restrict__ out)
{
    int p = blockIdx.x*256 + threadIdx.x;
    if (p >= HW) return;
    const int h = p >> 9, w = p & 511;

    // mask = lrelu(dot(t2[h,:,w], w_cl3[h,128,:]) + b_cl3[h,128])
    const float* tcol = t2 + (size_t)h*CHW + w;
    const float* wm = w_cl3 + (size_t)h*(129*128) + 128*128;
    float m = 0.f;
    #pragma unroll 8
    for (int c=0;c<CC;c++) m = fmaf(tcol[(size_t)c*WW], wm[c], m);
    m += b_cl3[h*129 + 128];
    out[HW + p] = lrelu(m);

    // regressor: n = w*448 + h; j = (n>>9)*128 + inds[flat n]
    const int n = w*HH + h;
    const int j = (n >> 9)*NCLS + inds[n];
    const float4* w2p = reinterpret_cast<const float4*>(w2 + (size_t)j*(CC*4));
    float4 a = *reinterpret_cast<const float4*>(b2 + 4*(size_t)j);
    const float* fcol = xr + (size_t)h*CHW + w;
    #pragma unroll 8
    for (int c=0;c<CC;c++){
        float x = fcol[(size_t)c*WW];
        float4 wv = w2p[c];
        a.x = fmaf(x, wv.x, a.x);
        a.y = fmaf(x, wv.y, a.y);
        a.z = fmaf(x, wv.z, a.z);
        a.w = fmaf(x, wv.w, a.w);
    }
    a.x = lrelu(a.x); a.y = lrelu(a.y); a.z = lrelu(a.z); a.w = lrelu(a.w);
    float4 w3v = *reinterpret_cast<const float4*>(w3 + 4*(size_t)j);
    float r = b3[j];
    r = fmaf(a.x, w3v.x, r); r = fmaf(a.y, w3v.y, r);
    r = fmaf(a.z, w3v.z, r); r = fmaf(a.w, w3v.w, r);
    out[p] = ((float)inds[p] + r) * (1.0f/128.0f);
}

extern "C" void kernel_launch(void* const* d_in, const int* in_sizes, int n_in,
                              void* d_out, int out_size)
{
    (void)in_sizes; (void)n_in; (void)out_size;
    const float* x_in  = (const float*)d_in[0];
    const float* w_cl1 = (const float*)d_in[1];
    const float* b_cl1 = (const float*)d_in[2];
    const float* w_cl2 = (const float*)d_in[3];
    const float* b_cl2 = (const float*)d_in[4];
    const float* w_cl3 = (const float*)d_in[5];
    const float* b_cl3 = (const float*)d_in[6];
    const float* w_reg1= (const float*)d_in[7];
    const float* b_reg1= (const float*)d_in[8];
    const float* w2    = (const float*)d_in[9];
    const float* b2    = (const float*)d_in[10];
    const float* w3    = (const float*)d_in[11];
    const float* b3    = (const float*)d_in[12];
    float* out = (float*)d_out;

    float *t1, *t2, *xr; int* inds;
    cudaGetSymbolAddress((void**)&t1, g_t1);
    cudaGetSymbolAddress((void**)&t2, g_t2);
    cudaGetSymbolAddress((void**)&xr, g_xr);
    cudaGetSymbolAddress((void**)&inds, g_inds);

    // x_in[c,h,w]: addr = c*(H*W) + h*W + w  ->  per-h base stride 512, row stride H*W
    // layer1 (cl1 -> t1) and reg1 (-> xr) share X tiles (interleaved in grid.x)
    k_gemm_lrelu<<<dim3(4, HH), 256>>>(x_in, (size_t)WW, (size_t)HW,
                                       w_cl1, b_cl1, t1,
                                       w_reg1, b_reg1, xr, 1);
    // layer2: t1 -> t2 (contiguous [h][c][w])
    k_gemm_lrelu<<<dim3(2, HH), 256>>>(t1, (size_t)CHW, (size_t)WW,
                                       w_cl2, b_cl2, t2,
                                       nullptr, nullptr, nullptr, 0);
    // layer3: t2 -> argmax indices (logits never hit DRAM)
    k_gemm_argmax<<<dim3(2, HH), 256>>>(t2, w_cl3, b_cl3, inds);
    // mask + regressor -> out[0:HW)=x_real, out[HW:2HW)=mask
    k_final<<<(HW+255)/256, 256>>>(xr, t2, w_cl3, b_cl3, inds, w2, b2, w3, b3, out);
}

// round 4
// speedup vs baseline: 1.1038x; 1.1038x over previous
#include <cuda_runtime.h>

#define HH 448
#define WW 512
#define CC 128
#define NCLS 128
#define TW 256
#define KC 16
#define HW (HH*WW)      // 229376
#define CHW (CC*WW)     // 65536

typedef unsigned long long ull;

// Scratch (allocation-free rule: __device__ globals)
__device__ float g_t1[HH*CC*WW];
__device__ float g_t2[HH*CC*WW];
__device__ float g_xr[HH*CC*WW];   // TRANSPOSED layout: [h][w][c]
__device__ int   g_inds[HW];

__device__ __forceinline__ ull pk2(float v){
    ull r; unsigned u = __float_as_uint(v);
    asm("mov.b64 %0, {%1, %1};" : "=l"(r) : "r"(u));
    return r;
}
__device__ __forceinline__ void fma2(ull& d, ull a, ull b){
    asm("fma.rn.f32x2 %0, %1, %2, %0;" : "+l"(d) : "l"(a), "l"(b));
}
__device__ __forceinline__ float2 up2(ull v){
    unsigned lo, hi;
    asm("mov.b64 {%0, %1}, %2;" : "=r"(lo), "=r"(hi) : "l"(v));
    return make_float2(__uint_as_float(lo), __uint_as_float(hi));
}
__device__ __forceinline__ float lrelu(float v){ return v >= 0.f ? v : 0.01f*v; }

// Core: one CTA computes a 128(O) x 256(W) tile for row h, K=128.
// If MASK: additionally accumulates mAcc[col=tid] = sum_k Xs[k][tid]*wsm[k]
// (the 129th classifier row), piggybacking on the resident X tile.
template<bool MASK>
__device__ __forceinline__ void gemm_core(
    const float* __restrict__ Xh, size_t xRS,
    const float* __restrict__ Wh,
    float (&Ws)[2][KC][128], float (&Xs)[2][KC][TW],
    ull (&acc)[8][8],
    const float* __restrict__ wsm, float& mAcc)
{
    const int tid = threadIdx.x;
    const int og = tid >> 4, wg = tid & 15;
    const int o0 = og << 3, t4 = wg << 2;
    const int xk = tid >> 4;            // Xs load: row within chunk
    const int xc = (tid & 15) << 2;     // Xs load: col base
    const int wq = tid & 3;             // Ws load: k-quad
    const int wo = tid >> 2;            // Ws load: o (0..63, +64)

    float4 xst[4];
    float4 wst[2];

    // prologue: chunk 0
    #pragma unroll
    for (int j = 0; j < 4; ++j)
        xst[j] = *reinterpret_cast<const float4*>(Xh + (size_t)xk * xRS + xc + 64*j);
    wst[0] = *reinterpret_cast<const float4*>(Wh + wo*128 + wq*4);
    wst[1] = *reinterpret_cast<const float4*>(Wh + (wo+64)*128 + wq*4);
    #pragma unroll
    for (int j = 0; j < 4; ++j)
        *reinterpret_cast<float4*>(&Xs[0][xk][xc + 64*j]) = xst[j];
    {
        const float* s0 = &wst[0].x;
        const float* s1 = &wst[1].x;
        #pragma unroll
        for (int i = 0; i < 4; ++i){
            int k = wq*4 + i;
            Ws[0][k][wo ^ (wq<<3)] = s0[i];          // XOR swizzle: conflict-free STS
            Ws[0][k][(wo+64) ^ (wq<<3)] = s1[i];
        }
    }
    __syncthreads();

    int buf = 0;
    #pragma unroll 1
    for (int ch = 0; ch < 8; ++ch){
        if (ch < 7){
            int k0 = (ch+1)*KC;
            #pragma unroll
            for (int j = 0; j < 4; ++j)
                xst[j] = *reinterpret_cast<const float4*>(Xh + (size_t)(k0 + xk) * xRS + xc + 64*j);
            wst[0] = *reinterpret_cast<const float4*>(Wh + wo*128 + k0 + wq*4);
            wst[1] = *reinterpret_cast<const float4*>(Wh + (wo+64)*128 + k0 + wq*4);
        }
        #pragma unroll
        for (int k = 0; k < KC; ++k){
            int wOff = ((k >> 2) & 3) << 3;
            const float4* wr = reinterpret_cast<const float4*>(&Ws[buf][k][o0 ^ wOff]);
            float4 wa = wr[0], wb = wr[1];
            float wv[8] = {wa.x,wa.y,wa.z,wa.w,wb.x,wb.y,wb.z,wb.w};
            ull xp[8];
            #pragma unroll
            for (int j = 0; j < 4; ++j){
                ulonglong2 v = *reinterpret_cast<const ulonglong2*>(&Xs[buf][k][t4 + 64*j]);
                xp[2*j] = v.x; xp[2*j+1] = v.y;
            }
            #pragma unroll
            for (int o = 0; o < 8; ++o){
                ull wp = pk2(wv[o]);
                #pragma unroll
                for (int p = 0; p < 8; ++p) fma2(acc[o][p], xp[p], wp);
            }
        }
        if (MASK){
            // 129th row dot-product, column = tid (ascending k preserves ref order)
            #pragma unroll
            for (int k = 0; k < KC; ++k)
                mAcc = fmaf(Xs[buf][k][tid], wsm[ch*KC + k], mAcc);
        }
        if (ch < 7){
            int nb = buf ^ 1;
            #pragma unroll
            for (int j = 0; j < 4; ++j)
                *reinterpret_cast<float4*>(&Xs[nb][xk][xc + 64*j]) = xst[j];
            const float* s0 = &wst[0].x;
            const float* s1 = &wst[1].x;
            #pragma unroll
            for (int i = 0; i < 4; ++i){
                int k = wq*4 + i;
                Ws[nb][k][wo ^ (wq<<3)] = s0[i];
                Ws[nb][k][(wo+64) ^ (wq<<3)] = s1[i];
            }
            __syncthreads();
            buf = nb;
        }
    }
}

// GEMM + bias + leaky-relu. If dual!=0, blockIdx.x selects (A/B) weight set
// interleaved so both read the same X tile back-to-back (L2 reuse).
// If transB and sel==1, output B is stored TRANSPOSED as [h][w][o] for the
// coalesced per-pixel gather in k_final.
__global__ void __launch_bounds__(256,1)
k_gemm_lrelu(const float* __restrict__ X, size_t xHS, size_t xRS,
             const float* __restrict__ WtA, const float* __restrict__ BtA, float* __restrict__ YA,
             const float* __restrict__ WtB, const float* __restrict__ BtB, float* __restrict__ YB,
             int dual, int transB)
{
    __shared__ __align__(16) float Ws[2][KC][128];
    __shared__ __align__(16) float Xs[2][KC][TW];
    int bx = blockIdx.x;
    int sel = 0, wTile;
    if (dual){ sel = bx & 1; wTile = bx >> 1; } else wTile = bx;
    const int h = blockIdx.y;
    const int wBase = wTile * TW;
    const float* Wt = sel ? WtB : WtA;
    const float* Bt = sel ? BtB : BtA;
    float* Y = sel ? YB : YA;

    ull acc[8][8];
    #pragma unroll
    for (int o=0;o<8;o++)
        #pragma unroll
        for (int p=0;p<8;p++) acc[o][p] = 0ull;

    const float* Xh = X + (size_t)h*xHS + wBase;
    const float* Wh = Wt + (size_t)h*(128*128);
    float mDummy = 0.f;
    gemm_core<false>(Xh, xRS, Wh, Ws, Xs, acc, nullptr, mDummy);

    const int tid = threadIdx.x;
    const int og = tid>>4, wg = tid&15;
    const int o0 = og<<3, t4 = wg<<2;

    float bias[8];
    #pragma unroll
    for (int o=0;o<8;o++) bias[o] = Bt[h*128 + o0 + o];

    if (sel == 1 && transB){
        // transposed store: element (o, w) -> Y[h*CHW + w*128 + o]
        #pragma unroll
        for (int j=0;j<4;j++){
            #pragma unroll
            for (int i=0;i<4;i++){
                int w = wBase + t4 + 64*j + i;
                float vv[8];
                #pragma unroll
                for (int o=0;o<8;o++){
                    float2 f = up2(acc[o][2*j + (i>>1)]);
                    float val = (i&1) ? f.y : f.x;
                    vv[o] = lrelu(val + bias[o]);
                }
                float* dst = Y + (size_t)h*CHW + (size_t)w*128 + o0;
                *reinterpret_cast<float4*>(dst)   = make_float4(vv[0],vv[1],vv[2],vv[3]);
                *reinterpret_cast<float4*>(dst+4) = make_float4(vv[4],vv[5],vv[6],vv[7]);
            }
        }
    } else {
        #pragma unroll
        for (int o=0;o<8;o++){
            float bo = bias[o];
            float* yo = Y + (size_t)h*CHW + (size_t)(o0+o)*WW + wBase;
            #pragma unroll
            for (int j=0;j<4;j++){
                float2 a = up2(acc[o][2*j]);
                float2 b = up2(acc[o][2*j+1]);
                float4 v;
                v.x = lrelu(a.x + bo); v.y = lrelu(a.y + bo);
                v.z = lrelu(b.x + bo); v.w = lrelu(b.y + bo);
                *reinterpret_cast<float4*>(yo + t4 + 64*j) = v;
            }
        }
    }
}

// Classifier GEMM (129-row weights) + fused in-CTA argmax + fused mask row.
// Tile covers all 128 classes x 256 cols, so argmax never leaves the CTA,
// and the 129th row (mask) is accumulated from the resident X tile.
__global__ void __launch_bounds__(256,1)
k_gemm_argmax(const float* __restrict__ X, const float* __restrict__ Wt,
              const float* __restrict__ Bt, int* __restrict__ inds,
              float* __restrict__ outMask /* = out + HW */)
{
    __shared__ __align__(16) float Ws[2][KC][128];
    __shared__ __align__(16) float Xs[2][KC][TW];
    __shared__ float wsm[128];
    const int wTile = blockIdx.x, h = blockIdx.y;
    const int wBase = wTile * TW;
    const int tid = threadIdx.x;

    if (tid < 128) wsm[tid] = Wt[(size_t)h*(129*128) + 128*128 + tid];
    // synced by first __syncthreads inside gemm_core

    ull acc[8][8];
    #pragma unroll
    for (int o=0;o<8;o++)
        #pragma unroll
        for (int p=0;p<8;p++) acc[o][p] = 0ull;

    const float* Xh = X + (size_t)h*CHW + wBase;
    const float* Wh = Wt + (size_t)h*(129*128);
    float mAcc = 0.f;
    gemm_core<true>(Xh, (size_t)WW, Wh, Ws, Xs, acc, wsm, mAcc);

    // mask output (column tid of this tile)
    outMask[(size_t)h*WW + wBase + tid] = lrelu(mAcc + Bt[h*129 + 128]);

    const int og = tid>>4, wg = tid&15;
    const int o0 = og<<3, t4 = wg<<2;

    // per-thread argmax over its 8 classes, per column (ascending class order,
    // strict > keeps the first max like jnp.argmax)
    float best[16]; int bidx[16];
    #pragma unroll
    for (int o=0;o<8;o++){
        float bo = Bt[h*129 + o0 + o];
        #pragma unroll
        for (int p=0;p<8;p++){
            float2 f = up2(acc[o][p]);
            float v0 = f.x + bo, v1 = f.y + bo;
            int c0 = 2*p, c1 = c0+1;
            if (o==0){ best[c0]=v0; bidx[c0]=o0; best[c1]=v1; bidx[c1]=o0; }
            else {
                if (v0 > best[c0]){ best[c0]=v0; bidx[c0]=o0+o; }
                if (v1 > best[c1]){ best[c1]=v1; bidx[c1]=o0+o; }
            }
        }
    }
    __syncthreads();   // done reading tiles; reuse smem for reduction

    float* rv = &Xs[0][0][0];                         // [16][256] values (16KB)
    int*   ri = reinterpret_cast<int*>(&Ws[0][0][0]); // [16][256] indices (16KB)
    #pragma unroll
    for (int lc=0; lc<16; ++lc){
        int w = t4 + 64*(lc>>2) + (lc&3);
        rv[og*TW + w] = best[lc];
        ri[og*TW + w] = bidx[lc];
    }
    __syncthreads();
    {
        int w = tid;                 // 256 threads, 256 columns
        float bv = rv[w]; int bi = ri[w];
        #pragma unroll
        for (int g=1; g<16; ++g){    // ascending class groups: ties keep first
            float v = rv[g*TW + w];
            int i = ri[g*TW + w];
            if (v > bv){ bv = v; bi = i; }
        }
        inds[h*WW + wBase + w] = bi;
    }
}

// Final: gathered per-pixel 128->4->1 regressor, warp-cooperative.
// One warp processes 32 consecutive pixels; per pixel the 32 lanes split the
// 128 input channels so the w2[j] row gather is fully coalesced (4 float4
// rounds), then a butterfly-shuffle reduces the 4-wide hidden vector.
// Reproduces the reference's index scramble: rows use n = w*448 + h, while
// inds_r interprets the same flat n as (h2, w2i) on a (448,512) grid.
__global__ void __launch_bounds__(256)
k_final(const float* __restrict__ xrT, const int* __restrict__ inds,
        const float* __restrict__ w2, const float* __restrict__ b2,
        const float* __restrict__ w3, const float* __restrict__ b3,
        float* __restrict__ out)
{
    const int warp = (blockIdx.x * blockDim.x + threadIdx.x) >> 5;
    const int lane = threadIdx.x & 31;
    const int base = warp * 32;
    if (base >= HW) return;

    float res = 0.f;
    #pragma unroll 1
    for (int i = 0; i < 32; ++i){
        const int p = base + i;
        const int h = p >> 9, w = p & 511;
        const int n = w*HH + h;
        const int j = (n >> 9)*NCLS + __ldg(&inds[n]);   // broadcast load

        const float4* wp = reinterpret_cast<const float4*>(w2 + (size_t)j*(CC*4));
        const float*  xp = xrT + (size_t)h*CHW + (size_t)w*128;

        float4 a = make_float4(0.f,0.f,0.f,0.f);
        #pragma unroll
        for (int r = 0; r < 4; ++r){
            int c = r*32 + lane;
            float  xv = __ldg(&xp[c]);      // coalesced 128B per round
            float4 wv = __ldg(&wp[c]);      // coalesced 512B per round
            a.x = fmaf(xv, wv.x, a.x);
            a.y = fmaf(xv, wv.y, a.y);
            a.z = fmaf(xv, wv.z, a.z);
            a.w = fmaf(xv, wv.w, a.w);
        }
        // butterfly reduction across the warp
        #pragma unroll
        for (int s = 16; s > 0; s >>= 1){
            a.x += __shfl_xor_sync(0xffffffffu, a.x, s);
            a.y += __shfl_xor_sync(0xffffffffu, a.y, s);
            a.z += __shfl_xor_sync(0xffffffffu, a.z, s);
            a.w += __shfl_xor_sync(0xffffffffu, a.w, s);
        }
        if (lane == i){
            float4 bb  = *reinterpret_cast<const float4*>(b2 + 4*(size_t)j);
            float h0 = lrelu(a.x + bb.x), h1 = lrelu(a.y + bb.y);
            float h2 = lrelu(a.z + bb.z), h3 = lrelu(a.w + bb.w);
            float4 w3v = *reinterpret_cast<const float4*>(w3 + 4*(size_t)j);
            float r2 = b3[j];
            r2 = fmaf(h0, w3v.x, r2); r2 = fmaf(h1, w3v.y, r2);
            r2 = fmaf(h2, w3v.z, r2); r2 = fmaf(h3, w3v.w, r2);
            res = ((float)inds[p] + r2) * (1.0f/128.0f);
        }
    }
    out[base + lane] = res;   // coalesced store of the warp's 32 results
}

extern "C" void kernel_launch(void* const* d_in, const int* in_sizes, int n_in,
                              void* d_out, int out_size)
{
    (void)in_sizes; (void)n_in; (void)out_size;
    const float* x_in  = (const float*)d_in[0];
    const float* w_cl1 = (const float*)d_in[1];
    const float* b_cl1 = (const float*)d_in[2];
    const float* w_cl2 = (const float*)d_in[3];
    const float* b_cl2 = (const float*)d_in[4];
    const float* w_cl3 = (const float*)d_in[5];
    const float* b_cl3 = (const float*)d_in[6];
    const float* w_reg1= (const float*)d_in[7];
    const float* b_reg1= (const float*)d_in[8];
    const float* w2    = (const float*)d_in[9];
    const float* b2    = (const float*)d_in[10];
    const float* w3    = (const float*)d_in[11];
    const float* b3    = (const float*)d_in[12];
    float* out = (float*)d_out;

    float *t1, *t2, *xr; int* inds;
    cudaGetSymbolAddress((void**)&t1, g_t1);
    cudaGetSymbolAddress((void**)&t2, g_t2);
    cudaGetSymbolAddress((void**)&xr, g_xr);
    cudaGetSymbolAddress((void**)&inds, g_inds);

    // x_in[c,h,w]: per-h base stride 512, row stride H*W
    // layer1 (cl1 -> t1) and reg1 (-> xr, TRANSPOSED) share X tiles
    k_gemm_lrelu<<<dim3(4, HH), 256>>>(x_in, (size_t)WW, (size_t)HW,
                                       w_cl1, b_cl1, t1,
                                       w_reg1, b_reg1, xr, 1, 1);
    // layer2: t1 -> t2 (contiguous [h][c][w])
    k_gemm_lrelu<<<dim3(2, HH), 256>>>(t1, (size_t)CHW, (size_t)WW,
                                       w_cl2, b_cl2, t2,
                                       nullptr, nullptr, nullptr, 0, 0);
    // layer3: t2 -> argmax indices + mask (logits never hit DRAM)
    k_gemm_argmax<<<dim3(2, HH), 256>>>(t2, w_cl3, b_cl3, inds, out + HW);
    // regressor -> out[0:HW)=x_real
    k_final<<<(HW/32 + 7)/8, 256>>>(xr, inds, w2, b2, w3, b3, out);
}